// round 1
// baseline (speedup 1.0000x reference)
#include <cuda_runtime.h>
#include <math_constants.h>

#define NSAMPLE 16
#define NPTS    8192
#define BATCH   2
#define CH      64
#define OUTCH   128
#define PPB     4        // points per block in feature kernel

// scratch for knn indices: [dir][batch][n][k]
__device__ int g_knn[2 * BATCH * NPTS * NSAMPLE];

// ---------------------------------------------------------------------------
// KNN: for each query point, exact top-16 nearest (squared distance) in the
// other cloud. Replace-max set maintenance; strict < keeps lower index on
// ties (matches stable top_k at the boundary; neighbor order itself is
// irrelevant downstream: gather + max-pool are permutation invariant).
// ---------------------------------------------------------------------------
__global__ void knn_kernel(const float* __restrict__ pc1,
                           const float* __restrict__ pc2) {
    const int dir = blockIdx.z;
    const int b   = blockIdx.y;
    const int n   = blockIdx.x * blockDim.x + threadIdx.x;

    const float* Q = dir ? pc2 : pc1;
    const float* P = dir ? pc1 : pc2;

    const float* qp = Q + ((size_t)b * NPTS + n) * 3;
    const float qx = qp[0], qy = qp[1], qz = qp[2];
    const float sq1 = qx * qx + qy * qy + qz * qz;

    __shared__ float sx[512], sy[512], sz[512], ss[512];

    float bd[NSAMPLE];
    int   bi[NSAMPLE];
#pragma unroll
    for (int k = 0; k < NSAMPLE; k++) { bd[k] = CUDART_INF_F; bi[k] = 0; }
    int   maxp = 0;
    float wd   = CUDART_INF_F;

    const float* Pb = P + (size_t)b * NPTS * 3;
    for (int t0 = 0; t0 < NPTS; t0 += 512) {
        for (int i = threadIdx.x; i < 512; i += blockDim.x) {
            float x = Pb[(t0 + i) * 3 + 0];
            float y = Pb[(t0 + i) * 3 + 1];
            float z = Pb[(t0 + i) * 3 + 2];
            sx[i] = x; sy[i] = y; sz[i] = z;
            ss[i] = x * x + y * y + z * z;
        }
        __syncthreads();
#pragma unroll 4
        for (int j = 0; j < 512; j++) {
            float dot = qx * sx[j] + qy * sy[j] + qz * sz[j];
            float d   = sq1 + ss[j] - 2.0f * dot;
            if (d < wd) {
                bd[maxp] = d;
                bi[maxp] = t0 + j;
                float m = bd[0]; int mp = 0;
#pragma unroll
                for (int k = 1; k < NSAMPLE; k++) {
                    if (bd[k] > m) { m = bd[k]; mp = k; }
                }
                wd = m; maxp = mp;
            }
        }
        __syncthreads();
    }

    int* outp = g_knn + (((size_t)dir * BATCH + b) * NPTS + n) * NSAMPLE;
#pragma unroll
    for (int k = 0; k < NSAMPLE; k++) outp[k] = bi[k];
}

// ---------------------------------------------------------------------------
// Fused feature kernel: gather neighbors, pos-MLP add, two 64x64 leaky
// layers, max over K, final 64->128 linear.
// Block = 256 threads = PPB(4) points x 64 channel-threads.
// Shared: transposed weights (w0T,w1T [c][o], twT [c][j]) + per-point
// activations hs[PPB][16][64] read as broadcast float4 in the GEMM loop.
// ---------------------------------------------------------------------------
__global__ void feat_kernel(const float* __restrict__ pc1,
                            const float* __restrict__ pc2,
                            const float* __restrict__ feat1,
                            const float* __restrict__ feat2,
                            const float* __restrict__ pos_w,
                            const float* __restrict__ pos_b,
                            const float* __restrict__ w0,
                            const float* __restrict__ b0,
                            const float* __restrict__ w1,
                            const float* __restrict__ b1,
                            const float* __restrict__ t1w,
                            const float* __restrict__ t1b,
                            const float* __restrict__ t2w,
                            const float* __restrict__ t2b,
                            float* __restrict__ out) {
    extern __shared__ float sm[];
    float* w0T   = sm;                       // 4096
    float* w1T   = w0T + 4096;               // 4096
    float* twT   = w1T + 4096;               // 8192
    float* hs    = twT + 8192;               // PPB*16*64 = 4096 (16B aligned)
    float* ms    = hs + PPB * 16 * 64;       // 256
    float* posws = ms + 256;                 // 192
    float* posbs = posws + 192;              // 64
    float* b0s   = posbs + 64;               // 64
    float* b1s   = b0s + 64;                 // 64
    float* tbs   = b1s + 64;                 // 128

    const int dir = blockIdx.z;
    const int b   = blockIdx.y;
    const int tid = threadIdx.x;

    const float* tw = dir ? t2w : t1w;
    const float* tb = dir ? t2b : t1b;

    // cooperative loads (transpose weights)
    for (int i = tid; i < 4096; i += 256) {
        int o = i >> 6, c = i & 63;
        w0T[c * 64 + o] = w0[i];
        w1T[c * 64 + o] = w1[i];
    }
    for (int i = tid; i < 8192; i += 256) {
        int j = i >> 6, c = i & 63;
        twT[c * 128 + j] = tw[i];
    }
    for (int i = tid; i < 192; i += 256) posws[i] = pos_w[i];
    if (tid < 64) {
        posbs[tid] = pos_b[tid];
        b0s[tid]   = b0[tid];
        b1s[tid]   = b1[tid];
    }
    if (tid < 128) tbs[tid] = tb[tid];
    __syncthreads();

    const int p = tid >> 6;      // point within block
    const int o = tid & 63;      // channel
    const int n = blockIdx.x * PPB + p;

    const float* Q  = dir ? pc2 : pc1;    // query cloud
    const float* PX = dir ? pc1 : pc2;    // neighbor cloud
    const float* F1 = dir ? feat2 : feat1;  // query features
    const float* F2 = dir ? feat1 : feat2;  // neighbor features

    const int* kidx = g_knn + (((size_t)dir * BATCH + b) * NPTS + n) * NSAMPLE;

    const float* qp = Q + ((size_t)b * NPTS + n) * 3;
    const float qx = qp[0], qy = qp[1], qz = qp[2];
    const float p1o = F1[((size_t)b * NPTS + n) * 64 + o];
    const float pwx = posws[o * 3 + 0];
    const float pwy = posws[o * 3 + 1];
    const float pwz = posws[o * 3 + 2];
    const float pb  = posbs[o];

    float* hsp = hs + p * (16 * 64);

    // Stage 1: gather + pos feat + leaky  ->  hs[p][k][o]
#pragma unroll
    for (int k = 0; k < NSAMPLE; k++) {
        int id = kidx[k];
        const float* np = PX + ((size_t)b * NPTS + id) * 3;
        float dx = np[0] - qx, dy = np[1] - qy, dz = np[2] - qz;
        float g  = F2[((size_t)b * NPTS + id) * 64 + o];
        float h  = g + p1o + (pwx * dx + pwy * dy + pwz * dz + pb);
        hsp[k * 64 + o] = (h >= 0.0f) ? h : 0.1f * h;
    }
    __syncthreads();

    float acc[NSAMPLE];

    // ----- layer 1 -----
#pragma unroll
    for (int k = 0; k < NSAMPLE; k++) acc[k] = b0s[o];
    for (int c = 0; c < 64; c += 4) {
        float wa = w0T[(c + 0) * 64 + o];
        float wb = w0T[(c + 1) * 64 + o];
        float wc = w0T[(c + 2) * 64 + o];
        float wdd = w0T[(c + 3) * 64 + o];
#pragma unroll
        for (int k = 0; k < NSAMPLE; k++) {
            float4 v = *reinterpret_cast<const float4*>(&hsp[k * 64 + c]);
            acc[k] = fmaf(v.x, wa, acc[k]);
            acc[k] = fmaf(v.y, wb, acc[k]);
            acc[k] = fmaf(v.z, wc, acc[k]);
            acc[k] = fmaf(v.w, wdd, acc[k]);
        }
    }
    __syncthreads();   // all reads of hs done
#pragma unroll
    for (int k = 0; k < NSAMPLE; k++) {
        float h = acc[k];
        hsp[k * 64 + o] = (h >= 0.0f) ? h : 0.1f * h;
    }
    __syncthreads();

    // ----- layer 2 -----
#pragma unroll
    for (int k = 0; k < NSAMPLE; k++) acc[k] = b1s[o];
    for (int c = 0; c < 64; c += 4) {
        float wa = w1T[(c + 0) * 64 + o];
        float wb = w1T[(c + 1) * 64 + o];
        float wc = w1T[(c + 2) * 64 + o];
        float wdd = w1T[(c + 3) * 64 + o];
#pragma unroll
        for (int k = 0; k < NSAMPLE; k++) {
            float4 v = *reinterpret_cast<const float4*>(&hsp[k * 64 + c]);
            acc[k] = fmaf(v.x, wa, acc[k]);
            acc[k] = fmaf(v.y, wb, acc[k]);
            acc[k] = fmaf(v.z, wc, acc[k]);
            acc[k] = fmaf(v.w, wdd, acc[k]);
        }
    }

    // leaky + max over K
    float m = -CUDART_INF_F;
#pragma unroll
    for (int k = 0; k < NSAMPLE; k++) {
        float h = acc[k];
        h = (h >= 0.0f) ? h : 0.1f * h;
        m = fmaxf(m, h);
    }
    ms[p * 64 + o] = m;
    __syncthreads();

    // ----- final 64 -> 128 linear (each thread: outputs o and o+64) -----
    float a0 = tbs[o];
    float a1 = tbs[o + 64];
    const float* msp = ms + p * 64;
#pragma unroll 8
    for (int c = 0; c < 64; c++) {
        float mc = msp[c];
        a0 = fmaf(mc, twT[c * 128 + o], a0);
        a1 = fmaf(mc, twT[c * 128 + o + 64], a1);
    }

    float* op = out + ((size_t)dir * BATCH * NPTS + (size_t)b * NPTS + n) * OUTCH;
    op[o]      = a0;
    op[o + 64] = a1;
}

// ---------------------------------------------------------------------------
extern "C" void kernel_launch(void* const* d_in, const int* in_sizes, int n_in,
                              void* d_out, int out_size) {
    (void)in_sizes; (void)n_in; (void)out_size;
    const float* pc1   = (const float*)d_in[0];
    const float* pc2   = (const float*)d_in[1];
    const float* feat1 = (const float*)d_in[2];
    const float* feat2 = (const float*)d_in[3];
    const float* pos_w = (const float*)d_in[4];
    const float* pos_b = (const float*)d_in[5];
    const float* w0    = (const float*)d_in[6];
    const float* b0    = (const float*)d_in[7];
    const float* w1    = (const float*)d_in[8];
    const float* b1    = (const float*)d_in[9];
    const float* t1w   = (const float*)d_in[10];
    const float* t1b   = (const float*)d_in[11];
    const float* t2w   = (const float*)d_in[12];
    const float* t2b   = (const float*)d_in[13];
    float* out = (float*)d_out;

    // KNN: 128 queries/block
    dim3 gk(NPTS / 128, BATCH, 2);
    knn_kernel<<<gk, 128>>>(pc1, pc2);

    // Feature kernel: 85 KB dynamic shared
    const size_t smem = (4096 + 4096 + 8192 + PPB * 16 * 64 + 256 + 192 +
                         64 + 64 + 64 + 128) * sizeof(float);
    cudaFuncSetAttribute(feat_kernel,
                         cudaFuncAttributeMaxDynamicSharedMemorySize,
                         (int)smem);
    dim3 gf(NPTS / PPB, BATCH, 2);
    feat_kernel<<<gf, 256, smem>>>(pc1, pc2, feat1, feat2, pos_w, pos_b,
                                   w0, b0, w1, b1, t1w, t1b, t2w, t2b, out);
}

// round 2
// speedup vs baseline: 1.1488x; 1.1488x over previous
#include <cuda_runtime.h>
#include <math_constants.h>

#define NSAMPLE 16
#define NPTS    8192
#define BATCH   2
#define CH      64
#define OUTCH   128
#define PPB     4        // points per block in feature kernel
#define KTILE   1024     // knn candidate tile (float4)

// scratch
__device__ int    g_knn[2 * BATCH * NPTS * NSAMPLE];           // [dir][b][n][k]
__device__ float4 g_pts4[2 * BATCH * NPTS];                    // [cloud][b][n] (x,y,z,|p|^2)
__device__ float  g_ms[2 * BATCH * NPTS * CH];                 // max-pooled features

// ---------------------------------------------------------------------------
// pack: xyz + squared norm into float4, both clouds
// ---------------------------------------------------------------------------
__global__ void pack_kernel(const float* __restrict__ pc1,
                            const float* __restrict__ pc2) {
    int i = blockIdx.x * blockDim.x + threadIdx.x;
    if (i >= 2 * BATCH * NPTS) return;
    const float* src = (i < BATCH * NPTS) ? pc1 : pc2;
    int r = (i < BATCH * NPTS) ? i : (i - BATCH * NPTS);
    float x = src[r * 3 + 0];
    float y = src[r * 3 + 1];
    float z = src[r * 3 + 2];
    g_pts4[i] = make_float4(x, y, z, x * x + y * y + z * z);
}

// ---------------------------------------------------------------------------
// KNN: exact top-16 per query. Register-resident top-16 with predicated
// replace (no dynamic indexing -> no local memory) and a pairwise max-tree
// rescan (ILP-friendly). 1 LDS.128 per candidate.
// ---------------------------------------------------------------------------
__global__ void __launch_bounds__(128) knn_kernel() {
    const int dir = blockIdx.z;
    const int b   = blockIdx.y;
    const int n   = blockIdx.x * 128 + threadIdx.x;

    const float4* Qb = g_pts4 + (size_t)dir * BATCH * NPTS + (size_t)b * NPTS;
    const float4* Cb = g_pts4 + (size_t)(1 - dir) * BATCH * NPTS + (size_t)b * NPTS;

    const float4 q = Qb[n];
    const float sq1 = q.w;

    __shared__ float4 s4[KTILE];

    float bd[NSAMPLE];
    int   bi[NSAMPLE];
#pragma unroll
    for (int k = 0; k < NSAMPLE; k++) { bd[k] = CUDART_INF_F; bi[k] = 0; }
    float wd   = CUDART_INF_F;
    int   maxp = 0;

    for (int t0 = 0; t0 < NPTS; t0 += KTILE) {
        for (int i = threadIdx.x; i < KTILE; i += 128) s4[i] = Cb[t0 + i];
        __syncthreads();

#pragma unroll 4
        for (int j = 0; j < KTILE; j++) {
            float4 c = s4[j];
            float dot = fmaf(q.x, c.x, fmaf(q.y, c.y, q.z * c.z));
            float d   = fmaf(-2.0f, dot, sq1 + c.w);
            if (d < wd) {
                int idx = t0 + j;
                // predicated replace at slot maxp
#pragma unroll
                for (int k = 0; k < NSAMPLE; k++) {
                    bool s = (k == maxp);
                    bd[k] = s ? d   : bd[k];
                    bi[k] = s ? idx : bi[k];
                }
                // pairwise (value,index) max tree
                float v8[8]; int i8[8];
#pragma unroll
                for (int k = 0; k < 8; k++) {
                    bool s = bd[2*k+1] > bd[2*k];
                    v8[k] = s ? bd[2*k+1] : bd[2*k];
                    i8[k] = s ? 2*k+1     : 2*k;
                }
                float v4[4]; int i4[4];
#pragma unroll
                for (int k = 0; k < 4; k++) {
                    bool s = v8[2*k+1] > v8[2*k];
                    v4[k] = s ? v8[2*k+1] : v8[2*k];
                    i4[k] = s ? i8[2*k+1] : i8[2*k];
                }
                float v2[2]; int i2[2];
#pragma unroll
                for (int k = 0; k < 2; k++) {
                    bool s = v4[2*k+1] > v4[2*k];
                    v2[k] = s ? v4[2*k+1] : v4[2*k];
                    i2[k] = s ? i4[2*k+1] : i4[2*k];
                }
                bool s = v2[1] > v2[0];
                wd   = s ? v2[1] : v2[0];
                maxp = s ? i2[1] : i2[0];
            }
        }
        __syncthreads();
    }

    int* outp = g_knn + (((size_t)dir * BATCH + b) * NPTS + n) * NSAMPLE;
#pragma unroll
    for (int k = 0; k < NSAMPLE; k++) outp[k] = bi[k];
}

// ---------------------------------------------------------------------------
// Fused feature kernel: gather + pos-feat + 2x (64x64 leaky) + max over K.
// Block = 256 threads = 4 points. Stage 1 uses (point, channel) mapping;
// layers use 4o x 4k register tiling (64 threads/point). Result -> g_ms.
// smem ~54KB -> 3-4 blocks/SM.
// ---------------------------------------------------------------------------
__global__ void __launch_bounds__(256) feat_kernel(
        const float* __restrict__ feat1,
        const float* __restrict__ feat2,
        const float* __restrict__ pos_w,
        const float* __restrict__ pos_b,
        const float* __restrict__ w0,
        const float* __restrict__ b0,
        const float* __restrict__ w1,
        const float* __restrict__ b1) {
    extern __shared__ float sm[];
    float* w0T   = sm;                         // 4096  [c][o]
    float* w1T   = w0T + 4096;                 // 4096  [c][o]
    float* hs    = w1T + 4096;                 // PPB*16*64 = 4096
    float* pm    = hs + PPB * 1024;            // PPB*4*64  = 1024
    float* posws = pm + PPB * 256;             // 192
    float* posbs = posws + 192;                // 64
    float* b0s   = posbs + 64;                 // 64
    float* b1s   = b0s + 64;                   // 64

    const int dir = blockIdx.z;
    const int b   = blockIdx.y;
    const int tid = threadIdx.x;

    for (int i = tid; i < 4096; i += 256) {
        int o = i >> 6, c = i & 63;
        w0T[c * 64 + o] = w0[i];
        w1T[c * 64 + o] = w1[i];
    }
    if (tid < 192) posws[tid] = pos_w[tid];
    if (tid < 64) {
        posbs[tid] = pos_b[tid];
        b0s[tid]   = b0[tid];
        b1s[tid]   = b1[tid];
    }
    __syncthreads();

    const int p  = tid >> 6;
    const int tt = tid & 63;
    const int n  = blockIdx.x * PPB + p;

    const float* F1 = dir ? feat2 : feat1;   // query features
    const float* F2 = dir ? feat1 : feat2;   // neighbor features
    const float4* QC = g_pts4 + (size_t)dir * BATCH * NPTS + (size_t)b * NPTS;
    const float4* NC = g_pts4 + (size_t)(1 - dir) * BATCH * NPTS + (size_t)b * NPTS;

    const int* kidx = g_knn + (((size_t)dir * BATCH + b) * NPTS + n) * NSAMPLE;

    const float4 q  = QC[n];
    const float p1o = F1[((size_t)b * NPTS + n) * CH + tt];
    const float pwx = posws[tt * 3 + 0];
    const float pwy = posws[tt * 3 + 1];
    const float pwz = posws[tt * 3 + 2];
    const float pb  = posbs[tt];

    float* hsp = hs + p * 1024;

    // ---- stage 1: gather + pos feat + leaky ----
#pragma unroll
    for (int k = 0; k < NSAMPLE; k++) {
        int id = kidx[k];
        float4 c = NC[id];
        float dx = c.x - q.x, dy = c.y - q.y, dz = c.z - q.z;
        float g  = F2[((size_t)b * NPTS + id) * CH + tt];
        float h  = g + p1o + fmaf(pwx, dx, fmaf(pwy, dy, fmaf(pwz, dz, pb)));
        hsp[k * 64 + tt] = (h >= 0.0f) ? h : 0.1f * h;
    }
    __syncthreads();

    // ---- layers: 4o x 4k register tiling ----
    const int o0 = (tt & 15) * 4;
    const int k0 = (tt >> 4) * 4;

    float acc[4][4];

    // layer 1
#pragma unroll
    for (int ki = 0; ki < 4; ki++)
#pragma unroll
        for (int oi = 0; oi < 4; oi++) acc[ki][oi] = b0s[o0 + oi];

    for (int c = 0; c < 64; c += 4) {
        float4 wv[4], hv[4];
#pragma unroll
        for (int i = 0; i < 4; i++)
            wv[i] = *reinterpret_cast<const float4*>(&w0T[(c + i) * 64 + o0]);
#pragma unroll
        for (int ki = 0; ki < 4; ki++)
            hv[ki] = *reinterpret_cast<const float4*>(&hsp[(k0 + ki) * 64 + c]);
#pragma unroll
        for (int ki = 0; ki < 4; ki++) {
#pragma unroll
            for (int oi = 0; oi < 4; oi++) {
                float a = acc[ki][oi];
                a = fmaf(hv[ki].x, (&wv[0].x)[oi], a);
                a = fmaf(hv[ki].y, (&wv[1].x)[oi], a);
                a = fmaf(hv[ki].z, (&wv[2].x)[oi], a);
                a = fmaf(hv[ki].w, (&wv[3].x)[oi], a);
                acc[ki][oi] = a;
            }
        }
    }
    __syncthreads();
    // leaky + writeback
#pragma unroll
    for (int ki = 0; ki < 4; ki++) {
        float4 v;
        float a;
        a = acc[ki][0]; v.x = (a >= 0.0f) ? a : 0.1f * a;
        a = acc[ki][1]; v.y = (a >= 0.0f) ? a : 0.1f * a;
        a = acc[ki][2]; v.z = (a >= 0.0f) ? a : 0.1f * a;
        a = acc[ki][3]; v.w = (a >= 0.0f) ? a : 0.1f * a;
        *reinterpret_cast<float4*>(&hsp[(k0 + ki) * 64 + o0]) = v;
    }
    __syncthreads();

    // layer 2
#pragma unroll
    for (int ki = 0; ki < 4; ki++)
#pragma unroll
        for (int oi = 0; oi < 4; oi++) acc[ki][oi] = b1s[o0 + oi];

    for (int c = 0; c < 64; c += 4) {
        float4 wv[4], hv[4];
#pragma unroll
        for (int i = 0; i < 4; i++)
            wv[i] = *reinterpret_cast<const float4*>(&w1T[(c + i) * 64 + o0]);
#pragma unroll
        for (int ki = 0; ki < 4; ki++)
            hv[ki] = *reinterpret_cast<const float4*>(&hsp[(k0 + ki) * 64 + c]);
#pragma unroll
        for (int ki = 0; ki < 4; ki++) {
#pragma unroll
            for (int oi = 0; oi < 4; oi++) {
                float a = acc[ki][oi];
                a = fmaf(hv[ki].x, (&wv[0].x)[oi], a);
                a = fmaf(hv[ki].y, (&wv[1].x)[oi], a);
                a = fmaf(hv[ki].z, (&wv[2].x)[oi], a);
                a = fmaf(hv[ki].w, (&wv[3].x)[oi], a);
                acc[ki][oi] = a;
            }
        }
    }

    // leaky + max over this thread's 4 k, write partial max
    float* pmp = pm + p * 256 + (tt >> 4) * 64;
#pragma unroll
    for (int oi = 0; oi < 4; oi++) {
        float m = -CUDART_INF_F;
#pragma unroll
        for (int ki = 0; ki < 4; ki++) {
            float a = acc[ki][oi];
            a = (a >= 0.0f) ? a : 0.1f * a;
            m = fmaxf(m, a);
        }
        pmp[o0 + oi] = m;
    }
    __syncthreads();

    // final max over 4 k-groups, store to global
    const float* pmb = pm + p * 256;
    float mm = fmaxf(fmaxf(pmb[tt], pmb[64 + tt]),
                     fmaxf(pmb[128 + tt], pmb[192 + tt]));
    g_ms[(((size_t)dir * BATCH + b) * NPTS + n) * CH + tt] = mm;
}

// ---------------------------------------------------------------------------
// Final projection: [N x 64] @ [64 -> 128] + bias, per direction
// Block 256 threads = 2 half-blocks x 128 output channels, 32 points/block.
// ---------------------------------------------------------------------------
__global__ void __launch_bounds__(256) proj_kernel(
        const float* __restrict__ t1w, const float* __restrict__ t1b,
        const float* __restrict__ t2w, const float* __restrict__ t2b,
        float* __restrict__ out) {
    __shared__ float twS[64 * 128];   // [c][j]
    __shared__ float tbS[128];
    __shared__ float aS[2][64];

    const int dir = blockIdx.z;
    const int b   = blockIdx.y;
    const int tid = threadIdx.x;

    const float* tw = dir ? t2w : t1w;
    const float* tb = dir ? t2b : t1b;

    for (int i = tid; i < 8192; i += 256) {
        int j = i >> 6, c = i & 63;
        twS[c * 128 + j] = tw[i];
    }
    if (tid < 128) tbS[tid] = tb[tid];
    __syncthreads();

    const int j  = tid & 127;
    const int ph = tid >> 7;

    for (int pi = 0; pi < 16; pi++) {
        int n = blockIdx.x * 32 + ph * 16 + pi;
        if (j < 64)
            aS[ph][j] = g_ms[(((size_t)dir * BATCH + b) * NPTS + n) * CH + j];
        __syncthreads();
        float accu = tbS[j];
#pragma unroll
        for (int c = 0; c < 64; c++)
            accu = fmaf(aS[ph][c], twS[c * 128 + j], accu);
        out[(((size_t)dir * BATCH + b) * NPTS + n) * OUTCH + j] = accu;
        __syncthreads();
    }
}

// ---------------------------------------------------------------------------
extern "C" void kernel_launch(void* const* d_in, const int* in_sizes, int n_in,
                              void* d_out, int out_size) {
    (void)in_sizes; (void)n_in; (void)out_size;
    const float* pc1   = (const float*)d_in[0];
    const float* pc2   = (const float*)d_in[1];
    const float* feat1 = (const float*)d_in[2];
    const float* feat2 = (const float*)d_in[3];
    const float* pos_w = (const float*)d_in[4];
    const float* pos_b = (const float*)d_in[5];
    const float* w0    = (const float*)d_in[6];
    const float* b0    = (const float*)d_in[7];
    const float* w1    = (const float*)d_in[8];
    const float* b1    = (const float*)d_in[9];
    const float* t1w   = (const float*)d_in[10];
    const float* t1b   = (const float*)d_in[11];
    const float* t2w   = (const float*)d_in[12];
    const float* t2b   = (const float*)d_in[13];
    float* out = (float*)d_out;

    pack_kernel<<<(2 * BATCH * NPTS + 255) / 256, 256>>>(pc1, pc2);

    dim3 gk(NPTS / 128, BATCH, 2);
    knn_kernel<<<gk, 128>>>();

    const size_t smem = (4096 + 4096 + PPB * 1024 + PPB * 256 + 192 + 64 + 64 + 64)
                        * sizeof(float);
    cudaFuncSetAttribute(feat_kernel,
                         cudaFuncAttributeMaxDynamicSharedMemorySize, (int)smem);
    dim3 gf(NPTS / PPB, BATCH, 2);
    feat_kernel<<<gf, 256, smem>>>(feat1, feat2, pos_w, pos_b, w0, b0, w1, b1);

    dim3 gp(NPTS / 32, BATCH, 2);
    proj_kernel<<<gp, 256>>>(t1w, t1b, t2w, t2b, out);
}